// round 6
// baseline (speedup 1.0000x reference)
#include <cuda_runtime.h>
#include <float.h>

#define N 16384
#define H 64
#define EPSF 1e-8f
#define GRID 128
#define TPB 128
#define NB 65536  // buckets = top 16 bits of order-preserving key

// ---------------- scratch (device globals; no allocation allowed) ------------
__device__ float g_tmp[N];      // scattered (bucket-grouped) values
__device__ float g_sorted[N];   // fully sorted
__device__ int   g_cnt[NB];     // INVARIANT: zero at entry; re-zeroed before exit
__device__ int   g_off[NB];     // absolute exclusive prefix; mutated by scatter
__device__ int   g_btot[GRID];  // lookback slots (total+1); INVARIANT: zero at entry/exit
__device__ float g_pmse[GRID], g_pd2[GRID], g_pdens[GRID], g_pdmax[GRID];
__device__ unsigned g_arrive = 0;   // barrier arrival counter (self-resetting)
__device__ unsigned g_epoch  = 0;   // barrier epoch (monotonic, wrap-safe)
__device__ unsigned g_done   = 0;   // finalize counter; INVARIANT: zero at entry/exit

// ---------------- helpers -----------------------------------------------------
__device__ __forceinline__ float warp_sum(float v) {
#pragma unroll
    for (int o = 16; o > 0; o >>= 1) v += __shfl_xor_sync(0xffffffffu, v, o);
    return v;
}
__device__ __forceinline__ float warp_max(float v) {
#pragma unroll
    for (int o = 16; o > 0; o >>= 1) v = fmaxf(v, __shfl_xor_sync(0xffffffffu, v, o));
    return v;
}
__device__ __forceinline__ int warp_sumi(int v) {
#pragma unroll
    for (int o = 16; o > 0; o >>= 1) v += __shfl_xor_sync(0xffffffffu, v, o);
    return v;
}
__device__ __forceinline__ unsigned int okey(float f) {
    unsigned int u = __float_as_uint(f);
    return (u & 0x80000000u) ? ~u : (u | 0x80000000u);
}

// grid-wide barrier: all GRID blocks co-resident (GRID=128 < 148 SMs).
// __threadfence (gpu scope) orders this block's writes into L2 AND emits
// CCTL.IVALL (L1D invalidate), so post-barrier plain loads refetch from L2.
__device__ __forceinline__ void grid_sync(unsigned base, unsigned ph) {
    __syncthreads();
    if (threadIdx.x == 0) {
        __threadfence();
        unsigned a = atomicAdd(&g_arrive, 1);
        if (a == GRID - 1) {
            atomicExch(&g_arrive, 0);
            __threadfence();
            atomicAdd(&g_epoch, 1);     // release
        } else {
            while ((*(volatile unsigned*)&g_epoch) - base < ph) { }
        }
    }
    __syncthreads();
}

__global__ void __launch_bounds__(TPB, 1)
fused_kernel(const float* __restrict__ x,   const float* __restrict__ tgt,
             const float* __restrict__ w1,  const float* __restrict__ b1,
             const float* __restrict__ w2,  const float* __restrict__ b2,
             float* __restrict__ out) {
    __shared__ float sw1x2[H], sb1x2[H], sw2[H], sc2[H];
    __shared__ float sA[4], sB[4];
    __shared__ int   sI[4];
    __shared__ unsigned s_base;
    __shared__ int   s_final;

    const int tid = threadIdx.x;
    const int blk = blockIdx.x;
    const int gi  = blk * TPB + tid;
    const int lane = tid & 31, wid = tid >> 5;

    if (tid == 0) s_base = *(volatile unsigned*)&g_epoch;  // before any barrier completes

    if (tid < H) {
        float a = w1[tid];
        float c = w2[tid];
        sw1x2[tid] = a + a;            // fold the x2 of exp(2u) into weights
        sb1x2[tid] = 2.0f * b1[tid];
        sw2[tid] = c;
        sc2[tid] = -2.0f * c * a * a;  // coeff of t*(1-t^2) in d2y/dx2
    }
    __syncthreads();
    const unsigned base = s_base;

    // ---------------- phase 0: MLP partials + histogram -------------------------
    const float xv = x[gi];
    float pred = b2[0];
    float d2 = 0.0f;
#pragma unroll
    for (int h = 0; h < H; ++h) {
        float u2 = fmaf(xv, sw1x2[h], sb1x2[h]);          // 2*(x*w1+b1)
        float e  = __expf(u2);                            // FMUL + MUFU.EX2
        float t  = 1.0f - __fdividef(2.0f, e + 1.0f);     // tanh(u), ~2^-22 err
        pred = fmaf(sw2[h], t, pred);
        float t2 = t * t;
        float g  = fmaf(-t2, t, t);                       // t - t^3
        d2 = fmaf(sc2[h], g, d2);
    }
    {
        float err = pred - tgt[gi];
        float vm = warp_sum(err * err);
        float vd = warp_sum(d2 * d2);
        if (lane == 0) { sA[wid] = vm; sB[wid] = vd; }
        __syncthreads();
        if (tid == 0) {
            g_pmse[blk] = sA[0] + sA[1] + sA[2] + sA[3];
            g_pd2[blk]  = sB[0] + sB[1] + sB[2] + sB[3];
        }
    }
    const unsigned b = okey(xv) >> 16;
    atomicAdd(&g_cnt[b], 1);      // g_cnt zero at entry (invariant)

    grid_sync(base, 1);

    // ---------------- phase 1: block-local scan + decoupled lookback ------------
    int4 c4 = reinterpret_cast<const int4*>(g_cnt)[gi];
    int s = c4.x + c4.y + c4.z + c4.w;
    int inc = s;
#pragma unroll
    for (int o = 1; o < 32; o <<= 1) {
        int nb = __shfl_up_sync(0xffffffffu, inc, o);
        if (lane >= o) inc += nb;
    }
    if (lane == 31) sI[wid] = inc;
    __syncthreads();
    if (wid == 0 && lane < 4) {
        int v = sI[lane];
        int wi = v;
#pragma unroll
        for (int o = 1; o < 4; o <<= 1) {
            int nb = __shfl_up_sync(0x0000000fu, wi, o);
            if (lane >= o) wi += nb;
        }
        sI[lane] = wi - v;   // exclusive warp offsets
    }
    __syncthreads();
    int e_blk = sI[wid] + (inc - s);   // block-local exclusive base
    // publish block total (+1 so 0 means "not ready"); volatile = L1 bypass
    if (tid == TPB - 1) *(volatile int*)&g_btot[blk] = e_blk + s + 1;

    // lookback: poll only predecessors' totals (all blocks resident -> no deadlock)
    int pv = 0;
    if (tid < blk) {
        while ((pv = *(volatile int*)&g_btot[tid]) == 0) { }
        pv -= 1;
    }
    __syncthreads();   // sI reuse boundary
    pv = warp_sumi(pv);
    if (lane == 0) sI[wid] = pv;
    __syncthreads();
    {
        int bbase = sI[0] + sI[1] + sI[2] + sI[3];
        int4 o4;
        o4.x = bbase + e_blk;
        o4.y = o4.x + c4.x;
        o4.z = o4.y + c4.y;
        o4.w = o4.z + c4.z;
        reinterpret_cast<int4*>(g_off)[gi] = o4;
    }

    grid_sync(base, 2);

    // ---------------- phase 2: scatter -------------------------------------------
    {
        int pos = atomicAdd(&g_off[b], 1);
        g_tmp[pos] = xv;
    }

    grid_sync(base, 3);

    // ---------------- phase 3: rank-in-segment -----------------------------------
    {
        float v = g_tmp[gi];
        unsigned kv = okey(v);
        unsigned bb = kv >> 16;
        int en = g_off[bb];            // post-scatter: start + cnt
        int st = en - g_cnt[bb];
        int r = 0;
        for (int q = st; q < en; ++q) {
            unsigned kq = okey(g_tmp[q]);
            // equal keys are bit-identical floats -> deterministic final contents
            r += (kq < kv) || (kq == kv && q < gi);
        }
        g_sorted[st + r] = v;
    }

    grid_sync(base, 4);

    // ---------------- phase 4: density + restore invariants ----------------------
    reinterpret_cast<int4*>(g_cnt)[gi] = make_int4(0, 0, 0, 0);
    if (tid == 0) g_btot[blk] = 0;
    {
        float xi = g_sorted[gi];
        float c0 = (gi >= 1)     ? xi - g_sorted[gi - 1] : FLT_MAX;
        float c1 = (gi >= 2)     ? xi - g_sorted[gi - 2] : FLT_MAX;
        float c2 = (gi + 1 < N)  ? g_sorted[gi + 1] - xi : FLT_MAX;
        float c3 = (gi + 2 < N)  ? g_sorted[gi + 2] - xi : FLT_MAX;
        float m1 = fminf(c0, c2);
        float m2 = (c0 < c2) ? fminf(c1, c2) : fminf(c0, c3);
        float knn_mean = (m1 + m2 + 3.0f * EPSF) * (1.0f / 3.0f);
        float dens = 1.0f / (knn_mean + EPSF);

        float vs = warp_sum(dens);
        float vx = warp_max(dens);
        if (lane == 0) { sA[wid] = vs; sB[wid] = vx; }
        __syncthreads();
        if (tid == 0) {
            g_pdens[blk] = sA[0] + sA[1] + sA[2] + sA[3];
            g_pdmax[blk] = fmaxf(fmaxf(sB[0], sB[1]), fmaxf(sB[2], sB[3]));
        }
    }

    // ---------------- phase 5: last-arriving block finalizes ----------------------
    if (tid == 0) {
        __threadfence();                      // push partials to L2 + IVALL
        unsigned old = atomicAdd(&g_done, 1);
        s_final = (old == GRID - 1);
        if (s_final) atomicExch(&g_done, 0);  // reset invariant
    }
    __syncthreads();
    if (s_final) {
        float vm = __ldcg(&g_pmse[tid]);
        float vd = __ldcg(&g_pd2[tid]);
        float vs = __ldcg(&g_pdens[tid]);
        float vx = __ldcg(&g_pdmax[tid]);
        vm = warp_sum(vm);
        vd = warp_sum(vd);
        vs = warp_sum(vs);
        vx = warp_max(vx);
        if (lane == 0) { sA[wid] = vm; sB[wid] = vd; sw1x2[wid] = vs; sw2[wid] = vx; }
        __syncthreads();
        if (tid == 0) {
            float mse  = (sA[0] + sA[1] + sA[2] + sA[3]) * (1.0f / N);
            float md2  = (sB[0] + sB[1] + sB[2] + sB[3]) * (1.0f / N);
            float dsum = (sw1x2[0] + sw1x2[1] + sw1x2[2] + sw1x2[3]);
            float dmax = fmaxf(fmaxf(sw2[0], sw2[1]), fmaxf(sw2[2], sw2[3]));
            float mean_dnorm = (dsum * (1.0f / N)) / (dmax + EPSF);
            float mean_w = 1.0f + 0.1f * mean_dnorm;
            float penalty = 0.01f * mean_w * md2;
            out[0] = mse + penalty;
            out[1] = mse;
            out[2] = penalty;
        }
    }
}

// ---------------- launch ----------------------------------------------------------
extern "C" void kernel_launch(void* const* d_in, const int* in_sizes, int n_in,
                              void* d_out, int out_size) {
    const float* x   = (const float*)d_in[0];
    const float* tgt = (const float*)d_in[1];
    const float* w1  = (const float*)d_in[2];
    const float* b1  = (const float*)d_in[3];
    const float* w2  = (const float*)d_in[4];
    const float* b2  = (const float*)d_in[5];
    float* out = (float*)d_out;

    fused_kernel<<<GRID, TPB>>>(x, tgt, w1, b1, w2, b2, out);
    (void)in_sizes; (void)n_in; (void)out_size;
}

// round 7
// speedup vs baseline: 1.0865x; 1.0865x over previous
#include <cuda_runtime.h>
#include <float.h>

#define N 16384
#define H 64
#define EPSF 1e-8f
#define GRID 128
#define TPB 128
#define NB 65536  // buckets = top 16 bits of order-preserving key

// ---------------- scratch (device globals; no allocation allowed) ------------
__device__ float g_tmp[N];      // scattered (bucket-grouped) values
__device__ float g_sorted[N];   // fully sorted
__device__ int   g_cnt[NB];     // INVARIANT: zero at entry; re-zeroed before exit
__device__ int   g_off[NB];     // absolute exclusive prefix; mutated by scatter
__device__ int   g_btot[GRID];  // per-block totals (barrier-protected, overwritten)
__device__ float g_pmse[GRID], g_pd2[GRID], g_pdens[GRID], g_pdmax[GRID];
__device__ unsigned g_arrive = 0;   // barrier arrival counter (self-resetting)
__device__ unsigned g_epoch  = 0;   // barrier epoch (monotonic, wrap-safe)
__device__ unsigned g_done   = 0;   // finalize counter; INVARIANT: zero at entry/exit

// ---------------- helpers -----------------------------------------------------
__device__ __forceinline__ float warp_sum(float v) {
#pragma unroll
    for (int o = 16; o > 0; o >>= 1) v += __shfl_xor_sync(0xffffffffu, v, o);
    return v;
}
__device__ __forceinline__ float warp_max(float v) {
#pragma unroll
    for (int o = 16; o > 0; o >>= 1) v = fmaxf(v, __shfl_xor_sync(0xffffffffu, v, o));
    return v;
}
__device__ __forceinline__ int warp_sumi(int v) {
#pragma unroll
    for (int o = 16; o > 0; o >>= 1) v += __shfl_xor_sync(0xffffffffu, v, o);
    return v;
}
__device__ __forceinline__ unsigned int okey(float f) {
    unsigned int u = __float_as_uint(f);
    return (u & 0x80000000u) ? ~u : (u | 0x80000000u);
}

// grid-wide barrier: all GRID blocks co-resident (GRID=128 < 148 SMs).
// __threadfence (gpu scope) orders this block's writes into L2 AND emits
// CCTL.IVALL (L1D invalidate), so post-barrier plain loads refetch from L2.
__device__ __forceinline__ void grid_sync(unsigned base, unsigned ph) {
    __syncthreads();
    if (threadIdx.x == 0) {
        __threadfence();
        unsigned a = atomicAdd(&g_arrive, 1);
        if (a == GRID - 1) {
            atomicExch(&g_arrive, 0);
            __threadfence();
            atomicAdd(&g_epoch, 1);     // release
        } else {
            while ((*(volatile unsigned*)&g_epoch) - base < ph) { }
        }
    }
    __syncthreads();
}

__global__ void __launch_bounds__(TPB, 1)
fused_kernel(const float* __restrict__ x,   const float* __restrict__ tgt,
             const float* __restrict__ w1,  const float* __restrict__ b1,
             const float* __restrict__ w2,  const float* __restrict__ b2,
             float* __restrict__ out) {
    __shared__ float sw1x2[H], sb1x2[H], sw2[H], sc2[H];
    __shared__ float sA[4], sB[4];
    __shared__ int   sI[4];
    __shared__ unsigned s_base;
    __shared__ int   s_final;

    const int tid = threadIdx.x;
    const int blk = blockIdx.x;
    const int gi  = blk * TPB + tid;
    const int lane = tid & 31, wid = tid >> 5;

    if (tid == 0) s_base = *(volatile unsigned*)&g_epoch;  // before any barrier completes

    if (tid < H) {
        float a = w1[tid];
        float c = w2[tid];
        sw1x2[tid] = a + a;            // fold the x2 of exp(2u) into weights
        sb1x2[tid] = 2.0f * b1[tid];
        sw2[tid] = c;
        sc2[tid] = -2.0f * c * a * a;  // coeff of t*(1-t^2) in d2y/dx2
    }
    __syncthreads();
    const unsigned base = s_base;

    // ---------------- phase 0: MLP partials + histogram -------------------------
    const float xv = x[gi];
    float pred = b2[0];
    float d2 = 0.0f;
#pragma unroll
    for (int h = 0; h < H; ++h) {
        float u2 = fmaf(xv, sw1x2[h], sb1x2[h]);          // 2*(x*w1+b1)
        float e  = __expf(u2);                            // FMUL + MUFU.EX2
        float t  = 1.0f - __fdividef(2.0f, e + 1.0f);     // tanh(u), ~2^-22 err
        pred = fmaf(sw2[h], t, pred);
        float t2 = t * t;
        float g  = fmaf(-t2, t, t);                       // t - t^3
        d2 = fmaf(sc2[h], g, d2);
    }
    {
        float err = pred - tgt[gi];
        float vm = warp_sum(err * err);
        float vd = warp_sum(d2 * d2);
        if (lane == 0) { sA[wid] = vm; sB[wid] = vd; }
        __syncthreads();
        if (tid == 0) {
            g_pmse[blk] = sA[0] + sA[1] + sA[2] + sA[3];
            g_pd2[blk]  = sB[0] + sB[1] + sB[2] + sB[3];
        }
    }
    const unsigned b = okey(xv) >> 16;
    atomicAdd(&g_cnt[b], 1);      // g_cnt zero at entry (invariant)

    grid_sync(base, 1);

    // ---------------- phase 1a: block-local scan, publish block total -----------
    int4 c4 = reinterpret_cast<const int4*>(g_cnt)[gi];
    int s = c4.x + c4.y + c4.z + c4.w;
    int inc = s;
#pragma unroll
    for (int o = 1; o < 32; o <<= 1) {
        int nb = __shfl_up_sync(0xffffffffu, inc, o);
        if (lane >= o) inc += nb;
    }
    if (lane == 31) sI[wid] = inc;
    __syncthreads();
    if (wid == 0 && lane < 4) {
        int v = sI[lane];
        int wi = v;
#pragma unroll
        for (int o = 1; o < 4; o <<= 1) {
            int nb = __shfl_up_sync(0x0000000fu, wi, o);
            if (lane >= o) wi += nb;
        }
        sI[lane] = wi - v;   // exclusive warp offsets
    }
    __syncthreads();
    int e_blk = sI[wid] + (inc - s);   // block-local exclusive base
    if (tid == TPB - 1) g_btot[blk] = e_blk + s;

    grid_sync(base, 2);

    // ---------------- phase 1b: absolute offsets --------------------------------
    {
        int pv = (tid < blk) ? g_btot[tid] : 0;   // one coalesced read per thread
        pv = warp_sumi(pv);
        __syncthreads();   // sI reuse boundary
        if (lane == 0) sI[wid] = pv;
        __syncthreads();
        int bbase = sI[0] + sI[1] + sI[2] + sI[3];
        int4 o4;
        o4.x = bbase + e_blk;
        o4.y = o4.x + c4.x;
        o4.z = o4.y + c4.y;
        o4.w = o4.z + c4.z;
        reinterpret_cast<int4*>(g_off)[gi] = o4;
    }

    grid_sync(base, 3);

    // ---------------- phase 2: scatter -------------------------------------------
    {
        int pos = atomicAdd(&g_off[b], 1);
        g_tmp[pos] = xv;
    }

    grid_sync(base, 4);

    // ---------------- phase 3: rank-in-segment -----------------------------------
    {
        float v = g_tmp[gi];
        unsigned kv = okey(v);
        unsigned bb = kv >> 16;
        int en = g_off[bb];            // post-scatter: start + cnt
        int st = en - g_cnt[bb];
        int r = 0;
        for (int q = st; q < en; ++q) {
            unsigned kq = okey(g_tmp[q]);
            // equal keys are bit-identical floats -> deterministic final contents
            r += (kq < kv) || (kq == kv && q < gi);
        }
        g_sorted[st + r] = v;
    }

    grid_sync(base, 5);

    // ---------------- phase 4: density + restore g_cnt invariant -----------------
    reinterpret_cast<int4*>(g_cnt)[gi] = make_int4(0, 0, 0, 0);
    {
        float xi = g_sorted[gi];
        float c0 = (gi >= 1)     ? xi - g_sorted[gi - 1] : FLT_MAX;
        float c1 = (gi >= 2)     ? xi - g_sorted[gi - 2] : FLT_MAX;
        float c2 = (gi + 1 < N)  ? g_sorted[gi + 1] - xi : FLT_MAX;
        float c3 = (gi + 2 < N)  ? g_sorted[gi + 2] - xi : FLT_MAX;
        float m1 = fminf(c0, c2);
        float m2 = (c0 < c2) ? fminf(c1, c2) : fminf(c0, c3);
        float knn_mean = (m1 + m2 + 3.0f * EPSF) * (1.0f / 3.0f);
        float dens = 1.0f / (knn_mean + EPSF);

        float vs = warp_sum(dens);
        float vx = warp_max(dens);
        if (lane == 0) { sA[wid] = vs; sB[wid] = vx; }
        __syncthreads();
        if (tid == 0) {
            g_pdens[blk] = sA[0] + sA[1] + sA[2] + sA[3];
            g_pdmax[blk] = fmaxf(fmaxf(sB[0], sB[1]), fmaxf(sB[2], sB[3]));
        }
    }

    // ---------------- phase 5: last-arriving block finalizes ----------------------
    if (tid == 0) {
        __threadfence();                      // push partials to L2 + IVALL own L1
        unsigned old = atomicAdd(&g_done, 1);
        s_final = (old == GRID - 1);
        if (s_final) atomicExch(&g_done, 0);  // reset invariant
    }
    __syncthreads();
    if (s_final) {
        float vm = __ldcg(&g_pmse[tid]);
        float vd = __ldcg(&g_pd2[tid]);
        float vs = __ldcg(&g_pdens[tid]);
        float vx = __ldcg(&g_pdmax[tid]);
        vm = warp_sum(vm);
        vd = warp_sum(vd);
        vs = warp_sum(vs);
        vx = warp_max(vx);
        if (lane == 0) { sA[wid] = vm; sB[wid] = vd; sw1x2[wid] = vs; sw2[wid] = vx; }
        __syncthreads();
        if (tid == 0) {
            float mse  = (sA[0] + sA[1] + sA[2] + sA[3]) * (1.0f / N);
            float md2  = (sB[0] + sB[1] + sB[2] + sB[3]) * (1.0f / N);
            float dsum = (sw1x2[0] + sw1x2[1] + sw1x2[2] + sw1x2[3]);
            float dmax = fmaxf(fmaxf(sw2[0], sw2[1]), fmaxf(sw2[2], sw2[3]));
            float mean_dnorm = (dsum * (1.0f / N)) / (dmax + EPSF);
            float mean_w = 1.0f + 0.1f * mean_dnorm;
            float penalty = 0.01f * mean_w * md2;
            out[0] = mse + penalty;
            out[1] = mse;
            out[2] = penalty;
        }
    }
}

// ---------------- launch ----------------------------------------------------------
extern "C" void kernel_launch(void* const* d_in, const int* in_sizes, int n_in,
                              void* d_out, int out_size) {
    const float* x   = (const float*)d_in[0];
    const float* tgt = (const float*)d_in[1];
    const float* w1  = (const float*)d_in[2];
    const float* b1  = (const float*)d_in[3];
    const float* w2  = (const float*)d_in[4];
    const float* b2  = (const float*)d_in[5];
    float* out = (float*)d_out;

    fused_kernel<<<GRID, TPB>>>(x, tgt, w1, b1, w2, b2, out);
    (void)in_sizes; (void)n_in; (void)out_size;
}